// round 5
// baseline (speedup 1.0000x reference)
#include <cuda_runtime.h>

#define BB 32
#define MM 1024
#define NN 1024
#define DD 128
#define TM 128
#define TN 64
#define NT 512

typedef unsigned long long u64;

// ---------------- scratch ----------------
__device__ float g_sq[2][BB * MM];              // [0]=clip row norms, [1]=sent
__device__ float g_partial[2][BB][MM / TM];     // per-CTA loss partials

// ---------------- smem layout (floats) ----------------
#define SM_QT 0               /* 128x128 transposed+swizzled: 16384 */
#define SM_KT 16384           /* 64x128 transposed+swizzled:  8192 */
#define SM_VS 24576           /* 64x128 row-major:            8192 */
#define SM_PS 32768           /* 128x65:                      8320 */
#define SM_SQ 41088           /* 64 */
#define SM_CS 41152           /* 32 */
#define SMF   41184

// ---------------- f32x2 helpers ----------------
__device__ __forceinline__ u64 pack2(float lo, float hi) {
    u64 r; asm("mov.b64 %0, {%1, %2};" : "=l"(r) : "f"(lo), "f"(hi)); return r;
}
__device__ __forceinline__ u64 dup2(float v) {
    u64 r; asm("mov.b64 %0, {%1, %1};" : "=l"(r) : "f"(v)); return r;
}
__device__ __forceinline__ void unpack2(u64 p, float& lo, float& hi) {
    asm("mov.b64 {%0, %1}, %2;" : "=f"(lo), "=f"(hi) : "l"(p));
}
__device__ __forceinline__ u64 fma2(u64 a, u64 b, u64 c) {
    u64 d; asm("fma.rn.f32x2 %0, %1, %2, %3;" : "=l"(d) : "l"(a), "l"(b), "l"(c)); return d;
}
__device__ __forceinline__ u64 mul2(u64 a, u64 b) {
    u64 d; asm("mul.rn.f32x2 %0, %1, %2;" : "=l"(d) : "l"(a), "l"(b)); return d;
}

// ---------------- misc helpers ----------------
__device__ __forceinline__ float ex2(float x) {
    float y; asm("ex2.approx.ftz.f32 %0, %1;" : "=f"(y) : "f"(x)); return y;
}
__device__ __forceinline__ float rmax16(float v) {
#pragma unroll
    for (int o = 8; o; o >>= 1) v = fmaxf(v, __shfl_xor_sync(0xffffffffu, v, o));
    return v;
}
__device__ __forceinline__ float rsum16(float v) {
#pragma unroll
    for (int o = 8; o; o >>= 1) v += __shfl_xor_sync(0xffffffffu, v, o);
    return v;
}

// ---------------- row squared norms ----------------
__global__ void sq_kernel(const float* __restrict__ clip, const float* __restrict__ sent) {
    int gw = (blockIdx.x * blockDim.x + threadIdx.x) >> 5;
    int lane = threadIdx.x & 31;
    if (gw >= 2 * BB * MM) return;
    int sel = (gw >= BB * MM) ? 1 : 0;
    int row = sel ? (gw - BB * MM) : gw;
    const float* src = sel ? sent : clip;
    float4 v = ((const float4*)(src + (size_t)row * DD))[lane];
    float s = v.x * v.x + v.y * v.y + v.z * v.z + v.w * v.w;
#pragma unroll
    for (int o = 16; o > 0; o >>= 1) s += __shfl_xor_sync(0xffffffffu, s, o);
    if (lane == 0) g_sq[sel][row] = s;
}

// ---------------- GEMM1: S[128x64], 4x4 fragment per thread (512 thr) ----------------
// qT swizzle (32 granules/d): (m,d) at (d*32 + ((m>>2)^((d>>2)&31)))*4 + (m&3)
// kT swizzle (16 granules/d): (n,d) at (d*16 + ((n>>2)^((d>>2)&15)))*4 + (n&3)
// thread (ty=tid>>4 in 0..31, tx=tid&15): rows 4ty..+3, cols 4tx..+3
__device__ __forceinline__ void gemm1(const float4* __restrict__ qT4,
                                      const float4* __restrict__ kT4,
                                      int ty, int tx, u64 s2[2][4]) {
#pragma unroll
    for (int rp = 0; rp < 2; rp++)
#pragma unroll
        for (int c = 0; c < 4; c++) s2[rp][c] = 0ull;
#pragma unroll 2
    for (int d4 = 0; d4 < 32; ++d4) {
        int qg = ty ^ d4;
        int kg = tx ^ (d4 & 15);
#pragma unroll
        for (int j = 0; j < 4; ++j) {
            int d = 4 * d4 + j;
            float4 qa = qT4[d * 32 + qg];
            float4 kb = kT4[d * 16 + kg];
            u64 ap[2] = {pack2(qa.x, qa.y), pack2(qa.z, qa.w)};
            u64 bp[4] = {dup2(kb.x), dup2(kb.y), dup2(kb.z), dup2(kb.w)};
#pragma unroll
            for (int rp = 0; rp < 2; rp++)
#pragma unroll
                for (int c = 0; c < 4; c++) s2[rp][c] = fma2(ap[rp], bp[c], s2[rp][c]);
        }
    }
}

// ---------------- fused cycle kernel: soft-NN + expected-index ----------------
__global__ __launch_bounds__(NT, 1)
void fused_kernel(const float* __restrict__ clip, const float* __restrict__ sent,
                  const float* __restrict__ clip_lens, const float* __restrict__ sent_lens) {
    extern __shared__ float sm[];
    float* qT = sm + SM_QT;
    float* kT = sm + SM_KT;
    float* vs = sm + SM_VS;
    float* ps = sm + SM_PS;
    float* sq = sm + SM_SQ;
    float* cs = sm + SM_CS;
    const float4* qT4 = (const float4*)qT;
    const float4* kT4 = (const float4*)kT;
    const float4* vs4 = (const float4*)vs;

    const int cyc = blockIdx.z;
    const int b = blockIdx.y;
    const int r0 = blockIdx.x * TM;
    const float* qemb  = cyc ? sent : clip;
    const float* kvemb = cyc ? clip : sent;
    const int qsel = cyc, kvsel = cyc ^ 1;
    const int qlen  = (int)(cyc ? sent_lens[b] : clip_lens[b]);
    const int kvlen = (int)(cyc ? clip_lens[b] : sent_lens[b]);

    const int tid = threadIdx.x;
    const int tx = tid & 15, ty = tid >> 4;   // rows 4ty..+3 (S & acc), S cols 4tx..+3
    // GEMM2: same rows; d columns 8tx..8tx+7

    const float C2 = 1.4426950408889634f / 128.0f;   // log2(e)/D
    const float C1 = 2.0f * C2;

    // ---- load Q tile (transposed + swizzled) ----
    {
        const float4* q4 = (const float4*)(qemb + ((size_t)b * MM + r0) * DD);
#pragma unroll
        for (int it = 0; it < 8; ++it) {
            int t = tid + it * NT;
            int r = t >> 5, c4 = t & 31, ri = r & 3;
            float4 v = q4[t];
            int gb = (r >> 2) ^ c4;
            qT[((4 * c4 + 0) * 32 + gb) * 4 + ri] = v.x;
            qT[((4 * c4 + 1) * 32 + gb) * 4 + ri] = v.y;
            qT[((4 * c4 + 2) * 32 + gb) * 4 + ri] = v.z;
            qT[((4 * c4 + 3) * 32 + gb) * 4 + ri] = v.w;
        }
    }

    // ================= phase 1: soft-NN  (q vs kv) =================
    float m_i[4], l_i[4];
#pragma unroll
    for (int r = 0; r < 4; r++) { m_i[r] = -1e30f; l_i[r] = 0.f; }
    u64 acc2[4][4];                           // rows 4ty+rr, d pairs 8tx+2p
#pragma unroll
    for (int r = 0; r < 4; r++)
#pragma unroll
        for (int c = 0; c < 4; c++) acc2[r][c] = 0ull;

    const float4* kv4 = (const float4*)(kvemb + (size_t)b * NN * DD);
    const float* sqg = &g_sq[kvsel][b * NN];
    const int ntiles = (kvlen + TN - 1) / TN;

    float4 pf[4];
#pragma unroll
    for (int it = 0; it < 4; ++it) pf[it] = kv4[tid + it * NT];

    for (int t0 = 0; t0 < ntiles; ++t0) {
        const int n0 = t0 * TN;
        __syncthreads();   // prev GEMM2 done with kT/vs/ps
#pragma unroll
        for (int it = 0; it < 4; ++it) {
            int t = tid + it * NT;
            int r = t >> 5, c4 = t & 31, ri = r & 3;
            float4 v = pf[it];
            ((float4*)vs)[t] = v;
            int gb = (r >> 2) ^ (c4 & 15);
            kT[((4 * c4 + 0) * 16 + gb) * 4 + ri] = v.x;
            kT[((4 * c4 + 1) * 16 + gb) * 4 + ri] = v.y;
            kT[((4 * c4 + 2) * 16 + gb) * 4 + ri] = v.z;
            kT[((4 * c4 + 3) * 16 + gb) * 4 + ri] = v.w;
        }
        if (tid < TN) sq[tid] = sqg[n0 + tid] * C2;
        __syncthreads();
        if (t0 + 1 < ntiles) {   // prefetch next tile during compute
#pragma unroll
            for (int it = 0; it < 4; ++it)
                pf[it] = kv4[(size_t)(n0 + TN) * 32 + tid + it * NT];
        }

        u64 s2[2][4];
        gemm1(qT4, kT4, ty, tx, s2);
        float s[4][4];
#pragma unroll
        for (int rp = 0; rp < 2; rp++)
#pragma unroll
            for (int c = 0; c < 4; c++) unpack2(s2[rp][c], s[2 * rp][c], s[2 * rp + 1][c]);

        // ---- online softmax (base-2 domain) ----
        float scl[4];
        const bool full = (n0 + TN <= kvlen);
#pragma unroll
        for (int r = 0; r < 4; r++) {
            float mx = -1e30f;
            if (full) {
#pragma unroll
                for (int c = 0; c < 4; c++) {
                    float sc = fmaf(s[r][c], C1, -sq[4 * tx + c]);
                    s[r][c] = sc;
                    mx = fmaxf(mx, sc);
                }
            } else {
#pragma unroll
                for (int c = 0; c < 4; c++) {
                    int n = n0 + 4 * tx + c;
                    float sc = (n < kvlen) ? fmaf(s[r][c], C1, -sq[4 * tx + c]) : -1e30f;
                    s[r][c] = sc;
                    mx = fmaxf(mx, sc);
                }
            }
            mx = rmax16(mx);
            float nm = fmaxf(m_i[r], mx);
            scl[r] = ex2(m_i[r] - nm);
            float ts = 0.f;
#pragma unroll
            for (int c = 0; c < 4; c++) { float p = ex2(s[r][c] - nm); s[r][c] = p; ts += p; }
            ts = rsum16(ts);
            l_i[r] = l_i[r] * scl[r] + ts;
            m_i[r] = nm;
#pragma unroll
            for (int c = 0; c < 4; c++) ps[(4 * ty + r) * 65 + 4 * tx + c] = s[r][c];
        }
        __syncthreads();

        // ---- GEMM2: acc = acc*scale + P V  (rows shared with softmax: scl in regs) ----
#pragma unroll
        for (int rr = 0; rr < 4; rr++) {
            u64 rs = dup2(scl[rr]);
#pragma unroll
            for (int p = 0; p < 4; p++) acc2[rr][p] = mul2(acc2[rr][p], rs);
        }
#pragma unroll 4
        for (int n = 0; n < TN; ++n) {
            u64 prd[4];
#pragma unroll
            for (int rr = 0; rr < 4; rr++) prd[rr] = dup2(ps[(4 * ty + rr) * 65 + n]);
            float4 v0 = vs4[n * 32 + 2 * tx];
            float4 v1 = vs4[n * 32 + 2 * tx + 1];
            u64 vp[4] = {pack2(v0.x, v0.y), pack2(v0.z, v0.w),
                         pack2(v1.x, v1.y), pack2(v1.z, v1.w)};
#pragma unroll
            for (int rr = 0; rr < 4; rr++)
#pragma unroll
                for (int p = 0; p < 4; p++)
                    acc2[rr][p] = fma2(prd[rr], vp[p], acc2[rr][p]);
        }
    }

    // ---- phase-1 epilogue: nn = acc/l, write into qT (swizzled); l_i local ----
    __syncthreads();   // all GEMM2 (and thus all qT GEMM1 reads) complete
#pragma unroll
    for (int rr = 0; rr < 4; ++rr) {
        float inv = 1.0f / l_i[rr];
#pragma unroll
        for (int p = 0; p < 4; p++) {
            float f0, f1;
            unpack2(acc2[rr][p], f0, f1);
            int d = 8 * tx + 2 * p;
            int gb0 = ty ^ ((d >> 2) & 31);
            int gb1 = ty ^ (((d + 1) >> 2) & 31);
            qT[(d * 32 + gb0) * 4 + rr] = f0 * inv;
            qT[((d + 1) * 32 + gb1) * 4 + rr] = f1 * inv;
        }
    }

    // ================= phase 2: expected index  (nn vs q-embedding) =================
    float m2[4], l2[4], w2[4];
#pragma unroll
    for (int r = 0; r < 4; r++) { m2[r] = -1e30f; l2[r] = 0.f; w2[r] = 0.f; }

    const float4* kv24 = (const float4*)(qemb + (size_t)b * MM * DD);
    const float* sqg2 = &g_sq[qsel][b * MM];
    const int ntiles2 = (qlen + TN - 1) / TN;
#pragma unroll
    for (int it = 0; it < 4; ++it) pf[it] = kv24[tid + it * NT];

    for (int t0 = 0; t0 < ntiles2; ++t0) {
        const int n0 = t0 * TN;
        __syncthreads();   // covers qT epilogue writes (first iter) + prev GEMM1 kT reads
#pragma unroll
        for (int it = 0; it < 4; ++it) {
            int t = tid + it * NT;
            int r = t >> 5, c4 = t & 31, ri = r & 3;
            float4 v = pf[it];
            int gb = (r >> 2) ^ (c4 & 15);
            kT[((4 * c4 + 0) * 16 + gb) * 4 + ri] = v.x;
            kT[((4 * c4 + 1) * 16 + gb) * 4 + ri] = v.y;
            kT[((4 * c4 + 2) * 16 + gb) * 4 + ri] = v.z;
            kT[((4 * c4 + 3) * 16 + gb) * 4 + ri] = v.w;
        }
        if (tid < TN) sq[tid] = sqg2[n0 + tid] * C2;
        __syncthreads();
        if (t0 + 1 < ntiles2) {
#pragma unroll
            for (int it = 0; it < 4; ++it)
                pf[it] = kv24[(size_t)(n0 + TN) * 32 + tid + it * NT];
        }

        u64 s2[2][4];
        gemm1(qT4, kT4, ty, tx, s2);
        float s[4][4];
#pragma unroll
        for (int rp = 0; rp < 2; rp++)
#pragma unroll
            for (int c = 0; c < 4; c++) unpack2(s2[rp][c], s[2 * rp][c], s[2 * rp + 1][c]);

        const bool full = (n0 + TN <= qlen);
#pragma unroll
        for (int r = 0; r < 4; r++) {
            float mx = -1e30f;
            if (full) {
#pragma unroll
                for (int c = 0; c < 4; c++) {
                    float sc = fmaf(s[r][c], C1, -sq[4 * tx + c]);
                    s[r][c] = sc;
                    mx = fmaxf(mx, sc);
                }
            } else {
#pragma unroll
                for (int c = 0; c < 4; c++) {
                    int n = n0 + 4 * tx + c;
                    float sc = (n < qlen) ? fmaf(s[r][c], C1, -sq[4 * tx + c]) : -1e30f;
                    s[r][c] = sc;
                    mx = fmaxf(mx, sc);
                }
            }
            mx = rmax16(mx);
            float nm = fmaxf(m2[r], mx);
            float scl = ex2(m2[r] - nm);
            float ts = 0.f, tw = 0.f;
#pragma unroll
            for (int c = 0; c < 4; c++) {
                float p = ex2(s[r][c] - nm);
                ts += p;
                tw = fmaf(p, (float)(n0 + 4 * tx + c), tw);
            }
            ts = rsum16(ts);
            tw = rsum16(tw);
            l2[r] = l2[r] * scl + ts;
            w2[r] = w2[r] * scl + tw;
            m2[r] = nm;
        }
    }

    // ---- loss partial ----
    if (tx == 0) {
        float c = 0.f;
#pragma unroll
        for (int r = 0; r < 4; r++) {
            int ig = r0 + 4 * ty + r;
            if (ig < qlen) {
                float d = w2[r] / l2[r] - (float)ig;
                c = fmaf(d, d, c);
            }
        }
        cs[ty] = c;
    }
    __syncthreads();
    if (tid == 0) {
        float ssum = 0.f;
        for (int k = 0; k < 32; k++) ssum += cs[k];
        g_partial[cyc][b][blockIdx.x] = ssum;
    }
}

// ---------------- deterministic finalize ----------------
__global__ void finalize_kernel(const float* __restrict__ clip_lens,
                                const float* __restrict__ sent_lens,
                                float* __restrict__ out) {
    int b = threadIdx.x;  // 32 threads
#pragma unroll
    for (int cyc = 0; cyc < 2; ++cyc) {
        float s = 0.f;
        for (int k = 0; k < MM / TM; k++) s += g_partial[cyc][b][k];
        s /= (cyc ? sent_lens[b] : clip_lens[b]);
#pragma unroll
        for (int o = 16; o > 0; o >>= 1) s += __shfl_xor_sync(0xffffffffu, s, o);
        if (b == 0) out[cyc] = s / (float)BB;
        __syncwarp();
    }
}

// ---------------- launch ----------------
extern "C" void kernel_launch(void* const* d_in, const int* in_sizes, int n_in,
                              void* d_out, int out_size) {
    const float* clip      = (const float*)d_in[0];
    const float* clip_lens = (const float*)d_in[2];
    const float* sent      = (const float*)d_in[3];
    const float* sent_lens = (const float*)d_in[5];
    float* out = (float*)d_out;

    cudaFuncSetAttribute(fused_kernel, cudaFuncAttributeMaxDynamicSharedMemorySize,
                         SMF * 4);

    sq_kernel<<<(2 * BB * MM * 32) / 256, 256>>>(clip, sent);

    dim3 grid(MM / TM, BB, 2);
    fused_kernel<<<grid, NT, SMF * 4>>>(clip, sent, clip_lens, sent_lens);

    finalize_kernel<<<1, 32>>>(clip_lens, sent_lens, out);
}

// round 10
// speedup vs baseline: 1.6946x; 1.6946x over previous
#include <cuda_runtime.h>
#include <cuda_bf16.h>
#include <cstdint>

typedef unsigned long long u64;
typedef __nv_bfloat16 bf16;

#define BB 32
#define MM 1024
#define DD 128

// ===================== device scratch (no allocs allowed) =====================
__device__ bf16  g_hi[2][(size_t)BB * MM * DD];     // row-major splits [sel][b*M+r][d]
__device__ bf16  g_lo[2][(size_t)BB * MM * DD];
__device__ bf16  g_thi[2][(size_t)BB * DD * MM];    // transposed splits [sel][b*D+d][r]
__device__ bf16  g_tlo[2][(size_t)BB * DD * MM];
__device__ float g_S[(size_t)BB * MM * MM];         // score scratch (S then S2)
__device__ bf16  g_Phi[(size_t)BB * MM * MM];       // softmax weights hi split
__device__ bf16  g_Plo[(size_t)BB * MM * MM];       // lo split
__device__ bf16  g_NNhi[(size_t)BB * MM * DD];      // soft-NN splits
__device__ bf16  g_NNlo[(size_t)BB * MM * DD];
__device__ float g_sq[2][BB * MM];                  // row squared norms
__device__ float g_partial[2][BB][MM / 8];          // per-block loss partials

// ===================== helpers =====================
__device__ __forceinline__ uint32_t smem_u32(const void* p) {
    uint32_t a;
    asm("{ .reg .u64 t; cvta.to.shared.u64 t, %1; cvt.u32.u64 %0, t; }" : "=r"(a) : "l"(p));
    return a;
}
__device__ __forceinline__ float ex2(float x) {
    float y; asm("ex2.approx.ftz.f32 %0, %1;" : "=f"(y) : "f"(x)); return y;
}
__device__ __forceinline__ void ldm_x4(uint32_t& r0, uint32_t& r1, uint32_t& r2, uint32_t& r3,
                                       uint32_t addr) {
    asm volatile("ldmatrix.sync.aligned.m8n8.x4.shared.b16 {%0,%1,%2,%3}, [%4];"
                 : "=r"(r0), "=r"(r1), "=r"(r2), "=r"(r3) : "r"(addr));
}
__device__ __forceinline__ void mma16816(float* c, const uint32_t* a, const uint32_t* b) {
    asm volatile(
        "mma.sync.aligned.m16n8k16.row.col.f32.bf16.bf16.f32 "
        "{%0,%1,%2,%3}, {%4,%5,%6,%7}, {%8,%9}, {%0,%1,%2,%3};"
        : "+f"(c[0]), "+f"(c[1]), "+f"(c[2]), "+f"(c[3])
        : "r"(a[0]), "r"(a[1]), "r"(a[2]), "r"(a[3]), "r"(b[0]), "r"(b[1]));
}

#define C1F (2.0f * 1.4426950408889634f / 128.0f)
#define C2F (1.4426950408889634f / 128.0f)

// ===================== smem tile geometry =====================
#define TP  136                       /* padded row length in bf16 (272 B stride) */
#define TSZ (128 * TP)                /* elements per tile */
#define GSM_BYTES (4 * TSZ * 2)       /* A hi/lo + B hi/lo = 139264 B */

// gmem -> padded smem tile (128 rows x 128 bf16). row_stride_u4 = src row stride / 8 elems.
__device__ __forceinline__ void load_tile(const bf16* __restrict__ src, int row_stride_u4,
                                          bf16* __restrict__ dst, int tid) {
    const uint4* s4 = (const uint4*)src;
#pragma unroll
    for (int i = 0; i < 8; ++i) {
        int lin = tid + i * 256;          // 2048 uint4 total
        int rr = lin >> 4;                // row 0..127
        int cc = lin & 15;                // uint4 col
        uint4 v = s4[(size_t)rr * row_stride_u4 + cc];
        *(uint4*)(dst + rr * TP + cc * 8) = v;
    }
}

// ===================== warp MMA core: one 128x128x128 chunk =====================
// smem: A hi @0, A lo @TSZ, B hi @2*TSZ, B lo @3*TSZ (bf16 elements)
// warp (wm,wn) computes rows wm*64..+63, cols wn*32..+31 as 4x4 m16n8k16 tiles.
__device__ __forceinline__ void mma_chunk(uint32_t smb, int lane, int wm, int wn,
                                          float c[4][4][4]) {
    const uint32_t lrow = (uint32_t)(((lane & 15) * TP + 8 * (lane >> 4)) * 2);
    const uint32_t aB = smb + (uint32_t)(wm * 64 * TP * 2) + lrow;
    const uint32_t bB = smb + (uint32_t)(2 * TSZ * 2) + (uint32_t)(wn * 32 * TP * 2) + lrow;
#pragma unroll
    for (int ks = 0; ks < 8; ++ks) {
        const uint32_t kb = (uint32_t)(ks * 32);   // 16 bf16 = 32 bytes per k-step
        uint32_t ah[4][4], al[4][4], bh[4][2], bl[4][2];
#pragma unroll
        for (int mt = 0; mt < 4; ++mt) {
            ldm_x4(ah[mt][0], ah[mt][1], ah[mt][2], ah[mt][3],
                   aB + (uint32_t)(mt * 16 * TP * 2) + kb);
            ldm_x4(al[mt][0], al[mt][1], al[mt][2], al[mt][3],
                   aB + (uint32_t)(TSZ * 2) + (uint32_t)(mt * 16 * TP * 2) + kb);
        }
        ldm_x4(bh[0][0], bh[1][0], bh[0][1], bh[1][1], bB + kb);
        ldm_x4(bh[2][0], bh[3][0], bh[2][1], bh[3][1], bB + (uint32_t)(16 * TP * 2) + kb);
        ldm_x4(bl[0][0], bl[1][0], bl[0][1], bl[1][1], bB + (uint32_t)(TSZ * 2) + kb);
        ldm_x4(bl[2][0], bl[3][0], bl[2][1], bl[3][1],
               bB + (uint32_t)(TSZ * 2) + (uint32_t)(16 * TP * 2) + kb);
#pragma unroll
        for (int mt = 0; mt < 4; ++mt)
#pragma unroll
            for (int nt = 0; nt < 4; ++nt) {
                mma16816(c[mt][nt], ah[mt], bh[nt]);   // hi*hi
                mma16816(c[mt][nt], ah[mt], bl[nt]);   // hi*lo
                mma16816(c[mt][nt], al[mt], bh[nt]);   // lo*hi
            }
    }
}

// ===================== convert: fp32 -> bf16 hi/lo splits (+ transposed) =====================
__global__ void convert_kernel(const float* __restrict__ clip, const float* __restrict__ sent) {
    int sel = blockIdx.z, b = blockIdx.y, r0 = blockIdx.x * 128;
    const float* src = sel ? sent : clip;
    __shared__ bf16 shi[128][34];
    __shared__ bf16 slo[128][34];
    int t = threadIdx.x;
    for (int sub = 0; sub < 4; ++sub) {
        int rbase = r0 + sub * 32;
        int r = t >> 3;
        int d0 = (t & 7) * 16;
        const float* row = src + ((size_t)b * MM + rbase + r) * DD + d0;
        size_t obase = ((size_t)b * MM + rbase + r) * DD + d0;
#pragma unroll
        for (int j = 0; j < 16; ++j) {
            float x = row[j];
            bf16 h = __float2bfloat16(x);
            bf16 l = __float2bfloat16(x - __bfloat162float(h));
            g_hi[sel][obase + j] = h;
            g_lo[sel][obase + j] = l;
            shi[d0 + j][r] = h;
            slo[d0 + j][r] = l;
        }
        __syncthreads();
#pragma unroll
        for (int db = 0; db < 8; ++db) {
            int d = db * 16 + (t >> 4);
            int rr = (t & 15) * 2;
            uint32_t vh = *(const uint32_t*)&shi[d][rr];
            uint32_t vl = *(const uint32_t*)&slo[d][rr];
            *(uint32_t*)&g_thi[sel][((size_t)b * DD + d) * MM + rbase + rr] = vh;
            *(uint32_t*)&g_tlo[sel][((size_t)b * DD + d) * MM + rbase + rr] = vl;
        }
        __syncthreads();
    }
}

// ===================== row squared norms =====================
__global__ void sq_kernel(const float* __restrict__ clip, const float* __restrict__ sent) {
    int gw = (blockIdx.x * blockDim.x + threadIdx.x) >> 5;
    int lane = threadIdx.x & 31;
    if (gw >= 2 * BB * MM) return;
    int sel = (gw >= BB * MM) ? 1 : 0;
    int row = sel ? (gw - BB * MM) : gw;
    const float* src = sel ? sent : clip;
    float4 v = ((const float4*)(src + (size_t)row * DD))[lane];
    float s = v.x * v.x + v.y * v.y + v.z * v.z + v.w * v.w;
#pragma unroll
    for (int o = 16; o > 0; o >>= 1) s += __shfl_xor_sync(0xffffffffu, s, o);
    if (lane == 0) g_sq[sel][row] = s;
}

// ===================== S GEMM: out[m][n] = A[m] . B[n]  (K=128) =====================
__global__ __launch_bounds__(256, 1)
void gemm_s_kernel(const bf16* __restrict__ Ahi, const bf16* __restrict__ Alo,
                   const bf16* __restrict__ Bhi, const bf16* __restrict__ Blo,
                   float* __restrict__ out,
                   const float* __restrict__ lensM, const float* __restrict__ lensN) {
    extern __shared__ bf16 sm[];
    const int b = blockIdx.z, m0 = blockIdx.x * 128, n0 = blockIdx.y * 128;
    if (m0 >= (int)lensM[b] || n0 >= (int)lensN[b]) return;
    const int tid = threadIdx.x, lane = tid & 31, wid = tid >> 5;
    const int wm = wid & 1, wn = wid >> 1;

    load_tile(Ahi + ((size_t)b * MM + m0) * DD, DD / 8, sm, tid);
    load_tile(Alo + ((size_t)b * MM + m0) * DD, DD / 8, sm + TSZ, tid);
    load_tile(Bhi + ((size_t)b * MM + n0) * DD, DD / 8, sm + 2 * TSZ, tid);
    load_tile(Blo + ((size_t)b * MM + n0) * DD, DD / 8, sm + 3 * TSZ, tid);
    __syncthreads();

    float c[4][4][4];
#pragma unroll
    for (int mt = 0; mt < 4; ++mt)
#pragma unroll
        for (int nt = 0; nt < 4; ++nt)
#pragma unroll
            for (int k = 0; k < 4; ++k) c[mt][nt][k] = 0.f;

    mma_chunk(smem_u32(sm), lane, wm, wn, c);

    const int grp = lane >> 2, tig = lane & 3;
    float* ob = out + (size_t)b * MM * MM;
#pragma unroll
    for (int mt = 0; mt < 4; ++mt)
#pragma unroll
        for (int nt = 0; nt < 4; ++nt) {
            int row = m0 + wm * 64 + mt * 16 + grp;
            int col = n0 + wn * 32 + nt * 8 + tig * 2;
            *(float2*)&ob[(size_t)row * MM + col] = make_float2(c[mt][nt][0], c[mt][nt][1]);
            *(float2*)&ob[(size_t)(row + 8) * MM + col] = make_float2(c[mt][nt][2], c[mt][nt][3]);
        }
}

// ===================== softmax -> normalized P (hi/lo splits, zero tails) =====================
__global__ __launch_bounds__(256, 1)
void softmax_p_kernel(const float* __restrict__ lensQ, const float* __restrict__ lensKV, int kvsel) {
    const int b = blockIdx.y;
    const int m = blockIdx.x * 8 + (threadIdx.x >> 5);
    const int lane = threadIdx.x & 31;
    const int qlen = (int)lensQ[b], kvlen = (int)lensKV[b];
    if (m >= qlen) return;
    const float* Srow = g_S + ((size_t)b * MM + m) * MM;
    const float* sqr = g_sq[kvsel] + b * MM;
    float v[32], mx = -1e30f;
#pragma unroll
    for (int i = 0; i < 32; ++i) {
        int n = lane + i * 32;
        if (n < kvlen) {
            v[i] = fmaf(Srow[n], C1F, -C2F * sqr[n]);
            mx = fmaxf(mx, v[i]);
        } else v[i] = -1e30f;
    }
#pragma unroll
    for (int o = 16; o > 0; o >>= 1) mx = fmaxf(mx, __shfl_xor_sync(0xffffffffu, mx, o));
    float s = 0.f;
#pragma unroll
    for (int i = 0; i < 32; ++i) { float p = ex2(v[i] - mx); v[i] = p; s += p; }
#pragma unroll
    for (int o = 16; o > 0; o >>= 1) s += __shfl_xor_sync(0xffffffffu, s, o);
    const float inv = 1.0f / s;
    bf16* ph = g_Phi + ((size_t)b * MM + m) * MM;
    bf16* pl = g_Plo + ((size_t)b * MM + m) * MM;
#pragma unroll
    for (int i = 0; i < 32; ++i) {
        int n = lane + i * 32;
        float p = (n < kvlen) ? v[i] * inv : 0.f;
        bf16 h = __float2bfloat16(p);
        bf16 l = __float2bfloat16(p - __bfloat162float(h));
        ph[n] = h;
        pl[n] = l;
    }
}

// ===================== PV GEMM: nn[m][d] = sum_n P[m][n] * V[n][d] =====================
__global__ __launch_bounds__(256, 1)
void gemm_pv_kernel(const float* __restrict__ lensQ, const float* __restrict__ lensKV, int kvsel) {
    extern __shared__ bf16 sm[];
    const int b = blockIdx.z, m0 = blockIdx.x * 128;
    const int qlen = (int)lensQ[b], kvlen = (int)lensKV[b];
    if (m0 >= qlen) return;
    const int nch = (kvlen + 127) >> 7;
    const int tid = threadIdx.x, lane = tid & 31, wid = tid >> 5;
    const int wm = wid & 1, wn = wid >> 1;

    float c[4][4][4];
#pragma unroll
    for (int mt = 0; mt < 4; ++mt)
#pragma unroll
        for (int nt = 0; nt < 4; ++nt)
#pragma unroll
            for (int k = 0; k < 4; ++k) c[mt][nt][k] = 0.f;

    for (int ch = 0; ch < nch; ++ch) {
        if (ch) __syncthreads();
        const size_t po = ((size_t)b * MM + m0) * MM + ch * 128;
        const size_t vo = (size_t)b * DD * MM + ch * 128;
        load_tile(g_Phi + po, MM / 8, sm, tid);
        load_tile(g_Plo + po, MM / 8, sm + TSZ, tid);
        load_tile(g_thi[kvsel] + vo, MM / 8, sm + 2 * TSZ, tid);
        load_tile(g_tlo[kvsel] + vo, MM / 8, sm + 3 * TSZ, tid);
        __syncthreads();
        mma_chunk(smem_u32(sm), lane, wm, wn, c);
    }

    const int grp = lane >> 2, tig = lane & 3;
#pragma unroll
    for (int mt = 0; mt < 4; ++mt)
#pragma unroll
        for (int nt = 0; nt < 4; ++nt) {
            int row = m0 + wm * 64 + mt * 16 + grp;
            int col = wn * 32 + nt * 8 + tig * 2;   // d column (pair)
#pragma unroll
            for (int h = 0; h < 2; ++h) {
                float f0 = c[mt][nt][2 * h + 0], f1 = c[mt][nt][2 * h + 1];
                bf16 h0 = __float2bfloat16(f0);
                bf16 l0 = __float2bfloat16(f0 - __bfloat162float(h0));
                bf16 h1 = __float2bfloat16(f1);
                bf16 l1 = __float2bfloat16(f1 - __bfloat162float(h1));
                uint32_t pkh = (uint32_t)__bfloat16_as_ushort(h0) |
                               ((uint32_t)__bfloat16_as_ushort(h1) << 16);
                uint32_t pkl = (uint32_t)__bfloat16_as_ushort(l0) |
                               ((uint32_t)__bfloat16_as_ushort(l1) << 16);
                size_t o = ((size_t)b * MM + row + h * 8) * DD + col;
                *(uint32_t*)&g_NNhi[o] = pkh;
                *(uint32_t*)&g_NNlo[o] = pkl;
            }
        }
}

// ===================== expected index + loss partials from S2 =====================
__global__ __launch_bounds__(256, 1)
void idx_loss_kernel(const float* __restrict__ lensQ, int qsel, int cyc) {
    const int b = blockIdx.y;
    const int wy = threadIdx.x >> 5;
    const int m = blockIdx.x * 8 + wy;
    const int lane = threadIdx.x & 31;
    const int qlen = (int)lensQ[b];
    __shared__ float cs[8];
    float contrib = 0.f;
    if (m < qlen) {
        const float* Srow = g_S + ((size_t)b * MM + m) * MM;
        const float* sqr = g_sq[qsel] + b * MM;
        float v[32], mx = -1e30f;
#pragma unroll
        for (int i = 0; i < 32; ++i) {
            int n = lane + i * 32;
            if (n < qlen) {
                v[i] = fmaf(Srow[n], C1F, -C2F * sqr[n]);
                mx = fmaxf(mx, v[i]);
            } else v[i] = -1e30f;
        }
#pragma unroll
        for (int o = 16; o > 0; o >>= 1) mx = fmaxf(mx, __shfl_xor_sync(0xffffffffu, mx, o));
        float l = 0.f, w = 0.f;
#pragma unroll
        for (int i = 0; i < 32; ++i) {
            float p = ex2(v[i] - mx);
            l += p;
            w = fmaf(p, (float)(lane + i * 32), w);
        }
#pragma unroll
        for (int o = 16; o > 0; o >>= 1) {
            l += __shfl_xor_sync(0xffffffffu, l, o);
            w += __shfl_xor_sync(0xffffffffu, w, o);
        }
        float d = w / l - (float)m;
        contrib = d * d;
    }
    if (lane == 0) cs[wy] = contrib;
    __syncthreads();
    if (threadIdx.x == 0) {
        float s = 0.f;
#pragma unroll
        for (int k = 0; k < 8; ++k) s += cs[k];
        g_partial[cyc][b][blockIdx.x] = s;
    }
}

// ===================== deterministic finalize =====================
__global__ void finalize_kernel(const float* __restrict__ clip_lens,
                                const float* __restrict__ sent_lens,
                                float* __restrict__ out) {
    int b = threadIdx.x;  // 32 threads
#pragma unroll
    for (int cyc = 0; cyc < 2; ++cyc) {
        float s = 0.f;
        for (int k = 0; k < MM / 8; k++) s += g_partial[cyc][b][k];
        s /= (cyc ? sent_lens[b] : clip_lens[b]);
#pragma unroll
        for (int o = 16; o > 0; o >>= 1) s += __shfl_xor_sync(0xffffffffu, s, o);
        if (b == 0) out[cyc] = s / (float)BB;
        __syncwarp();
    }
}

// ===================== launch =====================
extern "C" void kernel_launch(void* const* d_in, const int* in_sizes, int n_in,
                              void* d_out, int out_size) {
    const float* clip      = (const float*)d_in[0];
    const float* clip_lens = (const float*)d_in[2];
    const float* sent      = (const float*)d_in[3];
    const float* sent_lens = (const float*)d_in[5];
    float* out = (float*)d_out;

    cudaFuncSetAttribute(gemm_s_kernel, cudaFuncAttributeMaxDynamicSharedMemorySize, GSM_BYTES);
    cudaFuncSetAttribute(gemm_pv_kernel, cudaFuncAttributeMaxDynamicSharedMemorySize, GSM_BYTES);

    convert_kernel<<<dim3(8, BB, 2), 256>>>(clip, sent);
    sq_kernel<<<(2 * BB * MM * 32) / 256, 256>>>(clip, sent);

    bf16 *hi0, *lo0, *nnh, *nnl;
    float* Sptr;
    cudaGetSymbolAddress((void**)&hi0, g_hi);
    cudaGetSymbolAddress((void**)&lo0, g_lo);
    cudaGetSymbolAddress((void**)&nnh, g_NNhi);
    cudaGetSymbolAddress((void**)&nnl, g_NNlo);
    cudaGetSymbolAddress((void**)&Sptr, g_S);
    bf16* hi1 = hi0 + (size_t)BB * MM * DD;
    bf16* lo1 = lo0 + (size_t)BB * MM * DD;

    for (int cyc = 0; cyc < 2; ++cyc) {
        const int kvsel = cyc ^ 1;
        const float* qlens  = cyc ? sent_lens : clip_lens;
        const float* kvlens = cyc ? clip_lens : sent_lens;
        const bf16* qhi = cyc ? hi1 : hi0;
        const bf16* qlo = cyc ? lo1 : lo0;
        const bf16* khi = kvsel ? hi1 : hi0;
        const bf16* klo = kvsel ? lo1 : lo0;

        // phase 1: S[m][n] = q[m] . kv[n]
        gemm_s_kernel<<<dim3(8, 8, BB), 256, GSM_BYTES>>>(qhi, qlo, khi, klo, Sptr, qlens, kvlens);
        softmax_p_kernel<<<dim3(MM / 8, BB), 256>>>(qlens, kvlens, kvsel);
        gemm_pv_kernel<<<dim3(8, 1, BB), 256, GSM_BYTES>>>(qlens, kvlens, kvsel);
        // phase 2: S2[m][n] = nn[m] . q[n]
        gemm_s_kernel<<<dim3(8, 8, BB), 256, GSM_BYTES>>>(nnh, nnl, qhi, qlo, Sptr, qlens, qlens);
        idx_loss_kernel<<<dim3(MM / 8, BB), 256>>>(qlens, cyc, cyc);
    }

    finalize_kernel<<<1, 32>>>(clip_lens, sent_lens, out);
}